// round 3
// baseline (speedup 1.0000x reference)
#include <cuda_runtime.h>
#include <cstdint>

// Problem constants
#define BB 64
#define UU 512
#define AE 1024
#define UE 256
#define AA 256           // head size / GEMM N
#define MTOT (BB*UU)     // 32768 rows

// Scratch (static device globals: no allocation)
__device__ float g_Q[(size_t)MTOT * AA];   // 33.5 MB
__device__ float g_K[(size_t)MTOT * AA];   // 33.5 MB

// ---------------------------------------------------------------------------
// Adaptive int width: reference says int64, but JAX without x64 emits int32.
// Values are in [0,512). For int64-LE data, every odd int32 word of the first
// 256 bytes is 0; for int32 data that's impossible in practice. Both reads
// stay in-bounds for their respective buffer sizes.
// ---------------------------------------------------------------------------
__device__ __forceinline__ bool counts_are_64bit(const int* p) {
    bool z = true;
    #pragma unroll
    for (int i = 1; i < 64; i += 2) z &= (p[i] == 0);
    return z;
}
__device__ __forceinline__ int load_count(const int* p, int b, bool is64) {
    return is64 ? p[2 * b] : p[b];
}

// ---------------------------------------------------------------------------
// Generic fused GEMM:  C[M,256] = concat(A0|A1)[M,Ktot] @ W[Ktot,256] + bias
// A0 covers k in [0,k0) with leading dim lda0; A1 covers [k0,Ktot) lda1.
// Tiles: BM=64, BN=64, BK=16; 256 threads; 4x4 per-thread micro-tile.
// ---------------------------------------------------------------------------
__global__ void __launch_bounds__(256)
gemm_bias_kernel(const float* __restrict__ A0, int lda0, int k0,
                 const float* __restrict__ A1, int lda1, int ktot,
                 const float* __restrict__ W, const float* __restrict__ bias,
                 float* __restrict__ C)
{
    __shared__ float As[16][65];   // [k][m], +1 pad to dodge STS conflicts
    __shared__ float Bs[16][64];   // [k][n], float4-friendly

    const int tid = threadIdx.x;
    const int tx = tid & 15;       // micro-tile col group
    const int ty = tid >> 4;       // micro-tile row group
    const int row0 = blockIdx.y * 64;
    const int col0 = blockIdx.x * 64;

    // Load index mapping
    const int lm = tid >> 2;           // 0..63 : A tile row
    const int lk = (tid & 3) * 4;      // 0,4,8,12 : A tile k base
    const int wk = tid >> 4;           // 0..15 : W tile k
    const int wn = (tid & 15) * 4;     // 0..60 : W tile n base

    float acc[4][4] = {};

    for (int kk = 0; kk < ktot; kk += 16) {
        // --- stage A tile (64 rows x 16 k), transposed into As[k][m]
        const float* src;
        int lda, colb;
        if (kk < k0) { src = A0; lda = lda0; colb = kk; }
        else         { src = A1; lda = lda1; colb = kk - k0; }
        float4 av = *(const float4*)&src[(size_t)(row0 + lm) * lda + colb + lk];
        As[lk + 0][lm] = av.x;
        As[lk + 1][lm] = av.y;
        As[lk + 2][lm] = av.z;
        As[lk + 3][lm] = av.w;
        // --- stage W tile (16 k x 64 n)
        float4 wv = *(const float4*)&W[(size_t)(kk + wk) * AA + col0 + wn];
        *(float4*)&Bs[wk][wn] = wv;
        __syncthreads();

        #pragma unroll
        for (int k = 0; k < 16; ++k) {
            float a0 = As[k][ty * 4 + 0];
            float a1 = As[k][ty * 4 + 1];
            float a2 = As[k][ty * 4 + 2];
            float a3 = As[k][ty * 4 + 3];
            float4 b4 = *(const float4*)&Bs[k][tx * 4];
            acc[0][0] += a0 * b4.x; acc[0][1] += a0 * b4.y; acc[0][2] += a0 * b4.z; acc[0][3] += a0 * b4.w;
            acc[1][0] += a1 * b4.x; acc[1][1] += a1 * b4.y; acc[1][2] += a1 * b4.z; acc[1][3] += a1 * b4.w;
            acc[2][0] += a2 * b4.x; acc[2][1] += a2 * b4.y; acc[2][2] += a2 * b4.z; acc[2][3] += a2 * b4.w;
            acc[3][0] += a3 * b4.x; acc[3][1] += a3 * b4.y; acc[3][2] += a3 * b4.z; acc[3][3] += a3 * b4.w;
        }
        __syncthreads();
    }

    // epilogue: add bias, store
    const int colb = col0 + tx * 4;
    float4 bb = *(const float4*)&bias[colb];
    #pragma unroll
    for (int r = 0; r < 4; ++r) {
        int row = row0 + ty * 4 + r;
        float4 v;
        v.x = acc[r][0] + bb.x;
        v.y = acc[r][1] + bb.y;
        v.z = acc[r][2] + bb.z;
        v.w = acc[r][3] + bb.w;
        *(float4*)&C[(size_t)row * AA + colb] = v;
    }
}

// ---------------------------------------------------------------------------
// Score GEMM (NT): S[b, q, k] = (Q_b @ K_b^T) / 16, masked, written to out.
// Tiles 64x64, BK=16; grid (8, 8, B).
// ---------------------------------------------------------------------------
__global__ void __launch_bounds__(256)
attn_kernel(const int* __restrict__ nr_own,
            const int* __restrict__ nr_enemy,
            const int* __restrict__ nr_flags,
            float* __restrict__ out)
{
    __shared__ float Qs[16][65];
    __shared__ float Ks[16][65];

    const int tid = threadIdx.x;
    const int tx = tid & 15;
    const int ty = tid >> 4;
    const int b  = blockIdx.z;
    const int row0 = blockIdx.y * 64;   // query rows
    const int col0 = blockIdx.x * 64;   // key cols

    const float* Qb = g_Q + (size_t)b * UU * AA;
    const float* Kb = g_K + (size_t)b * UU * AA;

    const int lm = tid >> 2;
    const int lk = (tid & 3) * 4;

    float acc[4][4] = {};

    for (int kk = 0; kk < AA; kk += 16) {
        float4 qv = *(const float4*)&Qb[(size_t)(row0 + lm) * AA + kk + lk];
        Qs[lk + 0][lm] = qv.x;
        Qs[lk + 1][lm] = qv.y;
        Qs[lk + 2][lm] = qv.z;
        Qs[lk + 3][lm] = qv.w;
        float4 kv = *(const float4*)&Kb[(size_t)(col0 + lm) * AA + kk + lk];
        Ks[lk + 0][lm] = kv.x;
        Ks[lk + 1][lm] = kv.y;
        Ks[lk + 2][lm] = kv.z;
        Ks[lk + 3][lm] = kv.w;
        __syncthreads();

        #pragma unroll
        for (int k = 0; k < 16; ++k) {
            float a0 = Qs[k][ty * 4 + 0];
            float a1 = Qs[k][ty * 4 + 1];
            float a2 = Qs[k][ty * 4 + 2];
            float a3 = Qs[k][ty * 4 + 3];
            float b0 = Ks[k][tx * 4 + 0];
            float b1 = Ks[k][tx * 4 + 1];
            float b2 = Ks[k][tx * 4 + 2];
            float b3 = Ks[k][tx * 4 + 3];
            acc[0][0] += a0 * b0; acc[0][1] += a0 * b1; acc[0][2] += a0 * b2; acc[0][3] += a0 * b3;
            acc[1][0] += a1 * b0; acc[1][1] += a1 * b1; acc[1][2] += a1 * b2; acc[1][3] += a1 * b3;
            acc[2][0] += a2 * b0; acc[2][1] += a2 * b1; acc[2][2] += a2 * b2; acc[2][3] += a2 * b3;
            acc[3][0] += a3 * b0; acc[3][1] += a3 * b1; acc[3][2] += a3 * b2; acc[3][3] += a3 * b3;
        }
        __syncthreads();
    }

    const bool is64 = counts_are_64bit(nr_own);
    const int fl = load_count(nr_flags, b, is64);
    const int ou = load_count(nr_own,   b, is64);
    const int en = load_count(nr_enemy, b, is64);

    float* outb = out + (size_t)b * UU * UU;
    #pragma unroll
    for (int r = 0; r < 4; ++r) {
        const int row = row0 + ty * 4 + r;
        const bool row_ok = (row >= fl) && (row < ou);
        float4 v;
        #pragma unroll
        for (int c = 0; c < 4; ++c) {
            const int col = col0 + tx * 4 + c;
            const bool ok = row_ok && (col < en);
            float s = acc[r][c] * 0.0625f;          // 1/sqrt(256)
            (&v.x)[c] = ok ? s : s * 1e-9f;          // mask multiplies logits
        }
        *(float4*)&outb[(size_t)row * UU + col0 + tx * 4] = v;
    }
}

// ---------------------------------------------------------------------------
// Row softmax in place: one block per row of 512 floats; 128 threads x float4.
// ---------------------------------------------------------------------------
__global__ void __launch_bounds__(128)
softmax_kernel(float* __restrict__ data)
{
    const size_t row = blockIdx.x;
    float* p = data + row * UU;
    const int tid = threadIdx.x;

    float4 v = ((float4*)p)[tid];
    float m = fmaxf(fmaxf(v.x, v.y), fmaxf(v.z, v.w));
    #pragma unroll
    for (int o = 16; o > 0; o >>= 1)
        m = fmaxf(m, __shfl_xor_sync(0xffffffffu, m, o));

    __shared__ float red[4];
    if ((tid & 31) == 0) red[tid >> 5] = m;
    __syncthreads();
    m = fmaxf(fmaxf(red[0], red[1]), fmaxf(red[2], red[3]));

    v.x = __expf(v.x - m);
    v.y = __expf(v.y - m);
    v.z = __expf(v.z - m);
    v.w = __expf(v.w - m);
    float s = v.x + v.y + v.z + v.w;
    #pragma unroll
    for (int o = 16; o > 0; o >>= 1)
        s += __shfl_xor_sync(0xffffffffu, s, o);

    __shared__ float red2[4];
    if ((tid & 31) == 0) red2[tid >> 5] = s;
    __syncthreads();
    s = red2[0] + red2[1] + red2[2] + red2[3];

    const float inv = 1.0f / s;
    v.x *= inv; v.y *= inv; v.z *= inv; v.w *= inv;
    ((float4*)p)[tid] = v;
}

// ---------------------------------------------------------------------------
extern "C" void kernel_launch(void* const* d_in, const int* in_sizes, int n_in,
                              void* d_out, int out_size)
{
    const float* ar    = (const float*)d_in[0];     // [B,U,AE]
    const float* own   = (const float*)d_in[1];     // [B,U,UE]
    const float* enemy = (const float*)d_in[2];     // [B,U,UE]
    const int* nro     = (const int*)d_in[3];       // [B,1] (int32 or int64, auto-detected)
    const int* nre     = (const int*)d_in[4];       // [B,1]
    const int* nrf     = (const int*)d_in[5];       // [B,1]
    const float* Wq    = (const float*)d_in[6];     // [1280,256]
    const float* bq    = (const float*)d_in[7];     // [256]
    const float* Wk    = (const float*)d_in[8];     // [256,256]
    const float* bk    = (const float*)d_in[9];     // [256]
    float* out = (float*)d_out;                     // [B,U,U]

    float* qptr; cudaGetSymbolAddress((void**)&qptr, g_Q);
    float* kptr; cudaGetSymbolAddress((void**)&kptr, g_K);

    // Q = concat(ar, own) @ Wq + bq
    {
        dim3 grid(AA / 64, MTOT / 64);
        gemm_bias_kernel<<<grid, 256>>>(ar, AE, AE, own, UE, AE + UE, Wq, bq, qptr);
    }
    // K = enemy @ Wk + bk
    {
        dim3 grid(AA / 64, MTOT / 64);
        gemm_bias_kernel<<<grid, 256>>>(enemy, UE, UE, enemy, UE, UE, Wk, bk, kptr);
    }
    // scores + mask
    {
        dim3 grid(UU / 64, UU / 64, BB);
        attn_kernel<<<grid, 256>>>(nro, nre, nrf, out);
    }
    // softmax rows
    softmax_kernel<<<MTOT, 128>>>(out);
}

// round 4
// speedup vs baseline: 1.9683x; 1.9683x over previous
#include <cuda_runtime.h>
#include <cuda_bf16.h>
#include <cstdint>

// Problem constants
#define BB 64
#define UU 512
#define AE 1024
#define UE 256
#define AA 256           // head size / GEMM N
#define MTOT (BB*UU)     // 32768 rows

// Q/K stored as bf16 hi/lo split pairs (x = hi + lo, error ~2^-17 rel)
__device__ __nv_bfloat16 g_Qhi[(size_t)MTOT * AA];
__device__ __nv_bfloat16 g_Qlo[(size_t)MTOT * AA];
__device__ __nv_bfloat16 g_Khi[(size_t)MTOT * AA];
__device__ __nv_bfloat16 g_Klo[(size_t)MTOT * AA];

// ---------------------------------------------------------------------------
// Adaptive int width (JAX w/o x64 silently emits int32 despite astype(int64)).
// ---------------------------------------------------------------------------
__device__ __forceinline__ bool counts_are_64bit(const int* p) {
    bool z = true;
    #pragma unroll
    for (int i = 1; i < 64; i += 2) z &= (p[i] == 0);
    return z;
}
__device__ __forceinline__ int load_count(const int* p, int b, bool is64) {
    return is64 ? p[2 * b] : p[b];
}

// ---------------------------------------------------------------------------
// MMA helpers
// ---------------------------------------------------------------------------
__device__ __forceinline__ void ldmx4(uint32_t* r, const void* ptr) {
    uint32_t a = (uint32_t)__cvta_generic_to_shared(ptr);
    asm volatile("ldmatrix.sync.aligned.m8n8.x4.shared.b16 {%0,%1,%2,%3}, [%4];"
                 : "=r"(r[0]), "=r"(r[1]), "=r"(r[2]), "=r"(r[3]) : "r"(a));
}
__device__ __forceinline__ void mma_bf16(float* d, const uint32_t* a, uint32_t b0, uint32_t b1) {
    asm volatile("mma.sync.aligned.m16n8k16.row.col.f32.bf16.bf16.f32 "
                 "{%0,%1,%2,%3}, {%4,%5,%6,%7}, {%8,%9}, {%0,%1,%2,%3};"
                 : "+f"(d[0]), "+f"(d[1]), "+f"(d[2]), "+f"(d[3])
                 : "r"(a[0]), "r"(a[1]), "r"(a[2]), "r"(a[3]), "r"(b0), "r"(b1));
}
__device__ __forceinline__ void split_bf16(float v, __nv_bfloat16& h, __nv_bfloat16& l) {
    h = __float2bfloat16(v);
    l = __float2bfloat16(v - __bfloat162float(h));
}

#define BM 128
#define BN 64
#define BK 16
#define LDT (BK + 8)     // smem row stride (bf16): 48 bytes -> conflict-free ldmatrix

// ---------------------------------------------------------------------------
// Projection GEMM, bf16 split-3:
//   C[M,256] = concat(A0|A1)[M,ktot] @ W[ktot,256] + bias
// Output written as bf16 hi/lo pair arrays. 256 threads, warp tile 32x32.
// ---------------------------------------------------------------------------
__global__ void __launch_bounds__(256)
proj_split3(const float* __restrict__ A0, int lda0, int k0,
            const float* __restrict__ A1, int lda1, int ktot,
            const float* __restrict__ W, const float* __restrict__ bias,
            __nv_bfloat16* __restrict__ Chi, __nv_bfloat16* __restrict__ Clo)
{
    __shared__ __align__(16) __nv_bfloat16 Ah[BM][LDT], Al[BM][LDT];
    __shared__ __align__(16) __nv_bfloat16 Bh[BN][LDT], Bl[BN][LDT];

    const int tid  = threadIdx.x;
    const int warp = tid >> 5, lane = tid & 31;
    const int wr = (warp >> 1) * 32;      // warp row within block tile
    const int wc = (warp & 1) * 32;       // warp col
    const int row0 = blockIdx.y * BM;
    const int col0 = blockIdx.x * BN;

    // A staging: 2 threads per row, 8 floats each
    const int arow = tid >> 1;
    const int ak   = (tid & 1) * 8;
    // W staging: thread -> (k = tid&15, 4 consecutive n)
    const int wk = tid & 15;
    const int wn = (tid >> 4) * 4;

    float acc[2][4][4] = {};

    float4 pa0, pa1, pw;

    auto loadA = [&](int kk) {
        const float* src; int lda, cb;
        if (kk < k0) { src = A0; lda = lda0; cb = kk; }
        else         { src = A1; lda = lda1; cb = kk - k0; }
        const float4* p = (const float4*)&src[(size_t)(row0 + arow) * lda + cb + ak];
        pa0 = p[0]; pa1 = p[1];
    };
    auto loadW = [&](int kk) {
        pw = *(const float4*)&W[(size_t)(kk + wk) * AA + col0 + wn];
    };
    auto stage = [&]() {
        #pragma unroll
        for (int j = 0; j < 4; ++j) {
            __nv_bfloat16 h, l;
            split_bf16((&pa0.x)[j], h, l);
            Ah[arow][ak + j] = h; Al[arow][ak + j] = l;
            split_bf16((&pa1.x)[j], h, l);
            Ah[arow][ak + 4 + j] = h; Al[arow][ak + 4 + j] = l;
            split_bf16((&pw.x)[j], h, l);
            Bh[wn + j][wk] = h; Bl[wn + j][wk] = l;   // transpose: [n][k]
        }
    };

    loadA(0); loadW(0);
    stage();
    __syncthreads();

    const int lrow = lane & 15;
    const int lcol = (lane >> 4) * 8;

    for (int kk = 0; kk < ktot; kk += BK) {
        const bool more = (kk + BK) < ktot;
        if (more) { loadA(kk + BK); loadW(kk + BK); }

        uint32_t ah[2][4], al2[2][4], bh[2][4], bl[2][4];
        #pragma unroll
        for (int mi = 0; mi < 2; ++mi) {
            ldmx4(ah[mi],  &Ah[wr + mi * 16 + lrow][lcol]);
            ldmx4(al2[mi], &Al[wr + mi * 16 + lrow][lcol]);
        }
        #pragma unroll
        for (int p = 0; p < 2; ++p) {
            ldmx4(bh[p], &Bh[wc + p * 16 + lrow][lcol]);
            ldmx4(bl[p], &Bl[wc + p * 16 + lrow][lcol]);
        }
        #pragma unroll
        for (int mi = 0; mi < 2; ++mi)
            #pragma unroll
            for (int p = 0; p < 2; ++p)
                #pragma unroll
                for (int t = 0; t < 2; ++t) {
                    float* d = acc[mi][p * 2 + t];
                    mma_bf16(d, ah[mi],  bh[p][t], bh[p][t + 2]);   // hi*hi
                    mma_bf16(d, ah[mi],  bl[p][t], bl[p][t + 2]);   // hi*lo
                    mma_bf16(d, al2[mi], bh[p][t], bh[p][t + 2]);   // lo*hi
                }
        __syncthreads();
        if (more) { stage(); __syncthreads(); }
    }

    // epilogue: +bias, split to hi/lo, store bf16x2 pairs
    #pragma unroll
    for (int mi = 0; mi < 2; ++mi)
        #pragma unroll
        for (int ni = 0; ni < 4; ++ni) {
            const int r = row0 + wr + mi * 16 + (lane >> 2);
            const int c = col0 + wc + ni * 8 + (lane & 3) * 2;
            const float b0 = bias[c], b1 = bias[c + 1];
            #pragma unroll
            for (int h = 0; h < 2; ++h) {           // rows r, r+8
                const int row = r + h * 8;
                float v0 = acc[mi][ni][h * 2 + 0] + b0;
                float v1 = acc[mi][ni][h * 2 + 1] + b1;
                __nv_bfloat16 h0, l0, h1, l1;
                split_bf16(v0, h0, l0);
                split_bf16(v1, h1, l1);
                __nv_bfloat162 hh; hh.x = h0; hh.y = h1;
                __nv_bfloat162 ll; ll.x = l0; ll.y = l1;
                *(__nv_bfloat162*)&Chi[(size_t)row * AA + c] = hh;
                *(__nv_bfloat162*)&Clo[(size_t)row * AA + c] = ll;
            }
        }
}

// ---------------------------------------------------------------------------
// Score GEMM (NT), bf16 split-3: S[b,q,k] = (Qb @ Kb^T)/16, masked.
// Q/K already bf16 hi/lo in globals. Block tile 128(q) x 64(k), 16 k-iters.
// ---------------------------------------------------------------------------
__global__ void __launch_bounds__(256)
attn_split3(const int* __restrict__ nr_own, const int* __restrict__ nr_enemy,
            const int* __restrict__ nr_flags, float* __restrict__ out)
{
    __shared__ __align__(16) __nv_bfloat16 Ah[BM][LDT], Al[BM][LDT];
    __shared__ __align__(16) __nv_bfloat16 Bh[BN][LDT], Bl[BN][LDT];

    const int tid  = threadIdx.x;
    const int warp = tid >> 5, lane = tid & 31;
    const int wr = (warp >> 1) * 32;
    const int wc = (warp & 1) * 32;
    const int b    = blockIdx.z;
    const int row0 = blockIdx.y * BM;   // queries
    const int col0 = blockIdx.x * BN;   // keys

    const __nv_bfloat16* Qh = g_Qhi + (size_t)b * UU * AA;
    const __nv_bfloat16* Ql = g_Qlo + (size_t)b * UU * AA;
    const __nv_bfloat16* Kh = g_Khi + (size_t)b * UU * AA;
    const __nv_bfloat16* Kl = g_Klo + (size_t)b * UU * AA;

    // A staging: uint4 = 8 bf16; 2 threads per row
    const int arow = tid >> 1;
    const int ak   = (tid & 1) * 8;
    // B staging: threads 0-127 -> Bh, 128-255 -> Bl
    const int bt   = tid & 127;
    const int brow = bt >> 1;
    const int bk   = (bt & 1) * 8;
    const __nv_bfloat16* Ksrc = (tid < 128) ? Kh : Kl;

    float acc[2][4][4] = {};
    uint4 pqh, pql, pk;

    auto loadG = [&](int kk) {
        pqh = *(const uint4*)&Qh[(size_t)(row0 + arow) * AA + kk + ak];
        pql = *(const uint4*)&Ql[(size_t)(row0 + arow) * AA + kk + ak];
        pk  = *(const uint4*)&Ksrc[(size_t)(col0 + brow) * AA + kk + bk];
    };
    auto stage = [&]() {
        *(uint4*)&Ah[arow][ak] = pqh;
        *(uint4*)&Al[arow][ak] = pql;
        if (tid < 128) *(uint4*)&Bh[brow][bk] = pk;
        else           *(uint4*)&Bl[brow][bk] = pk;
    };

    loadG(0);
    stage();
    __syncthreads();

    const int lrow = lane & 15;
    const int lcol = (lane >> 4) * 8;

    for (int kk = 0; kk < AA; kk += BK) {
        const bool more = (kk + BK) < AA;
        if (more) loadG(kk + BK);

        uint32_t ah[2][4], al2[2][4], bh[2][4], bl[2][4];
        #pragma unroll
        for (int mi = 0; mi < 2; ++mi) {
            ldmx4(ah[mi],  &Ah[wr + mi * 16 + lrow][lcol]);
            ldmx4(al2[mi], &Al[wr + mi * 16 + lrow][lcol]);
        }
        #pragma unroll
        for (int p = 0; p < 2; ++p) {
            ldmx4(bh[p], &Bh[wc + p * 16 + lrow][lcol]);
            ldmx4(bl[p], &Bl[wc + p * 16 + lrow][lcol]);
        }
        #pragma unroll
        for (int mi = 0; mi < 2; ++mi)
            #pragma unroll
            for (int p = 0; p < 2; ++p)
                #pragma unroll
                for (int t = 0; t < 2; ++t) {
                    float* d = acc[mi][p * 2 + t];
                    mma_bf16(d, ah[mi],  bh[p][t], bh[p][t + 2]);
                    mma_bf16(d, ah[mi],  bl[p][t], bl[p][t + 2]);
                    mma_bf16(d, al2[mi], bh[p][t], bh[p][t + 2]);
                }
        __syncthreads();
        if (more) { stage(); __syncthreads(); }
    }

    const bool is64 = counts_are_64bit(nr_own);
    const int fl = load_count(nr_flags, b, is64);
    const int ou = load_count(nr_own,   b, is64);
    const int en = load_count(nr_enemy, b, is64);

    float* outb = out + (size_t)b * UU * UU;
    #pragma unroll
    for (int mi = 0; mi < 2; ++mi)
        #pragma unroll
        for (int ni = 0; ni < 4; ++ni) {
            const int r = row0 + wr + mi * 16 + (lane >> 2);
            const int c = col0 + wc + ni * 8 + (lane & 3) * 2;
            #pragma unroll
            for (int h = 0; h < 2; ++h) {
                const int row = r + h * 8;
                const bool row_ok = (row >= fl) && (row < ou);
                float s0 = acc[mi][ni][h * 2 + 0] * 0.0625f;
                float s1 = acc[mi][ni][h * 2 + 1] * 0.0625f;
                s0 = (row_ok && (c     < en)) ? s0 : s0 * 1e-9f;
                s1 = (row_ok && (c + 1 < en)) ? s1 : s1 * 1e-9f;
                float2 v; v.x = s0; v.y = s1;
                *(float2*)&outb[(size_t)row * UU + c] = v;
            }
        }
}

// ---------------------------------------------------------------------------
// Row softmax in place: one block per row of 512 floats; 128 threads x float4.
// ---------------------------------------------------------------------------
__global__ void __launch_bounds__(128)
softmax_kernel(float* __restrict__ data)
{
    const size_t row = blockIdx.x;
    float* p = data + row * UU;
    const int tid = threadIdx.x;

    float4 v = ((float4*)p)[tid];
    float m = fmaxf(fmaxf(v.x, v.y), fmaxf(v.z, v.w));
    #pragma unroll
    for (int o = 16; o > 0; o >>= 1)
        m = fmaxf(m, __shfl_xor_sync(0xffffffffu, m, o));

    __shared__ float red[4];
    if ((tid & 31) == 0) red[tid >> 5] = m;
    __syncthreads();
    m = fmaxf(fmaxf(red[0], red[1]), fmaxf(red[2], red[3]));

    v.x = __expf(v.x - m);
    v.y = __expf(v.y - m);
    v.z = __expf(v.z - m);
    v.w = __expf(v.w - m);
    float s = v.x + v.y + v.z + v.w;
    #pragma unroll
    for (int o = 16; o > 0; o >>= 1)
        s += __shfl_xor_sync(0xffffffffu, s, o);

    __shared__ float red2[4];
    if ((tid & 31) == 0) red2[tid >> 5] = s;
    __syncthreads();
    s = red2[0] + red2[1] + red2[2] + red2[3];

    const float inv = 1.0f / s;
    v.x *= inv; v.y *= inv; v.z *= inv; v.w *= inv;
    ((float4*)p)[tid] = v;
}

// ---------------------------------------------------------------------------
extern "C" void kernel_launch(void* const* d_in, const int* in_sizes, int n_in,
                              void* d_out, int out_size)
{
    const float* ar    = (const float*)d_in[0];     // [B,U,AE]
    const float* own   = (const float*)d_in[1];     // [B,U,UE]
    const float* enemy = (const float*)d_in[2];     // [B,U,UE]
    const int* nro     = (const int*)d_in[3];       // [B,1] int32/int64 auto
    const int* nre     = (const int*)d_in[4];
    const int* nrf     = (const int*)d_in[5];
    const float* Wq    = (const float*)d_in[6];     // [1280,256]
    const float* bq    = (const float*)d_in[7];     // [256]
    const float* Wk    = (const float*)d_in[8];     // [256,256]
    const float* bk    = (const float*)d_in[9];     // [256]
    float* out = (float*)d_out;                     // [B,U,U]

    __nv_bfloat16 *qh, *ql, *kh, *kl;
    cudaGetSymbolAddress((void**)&qh, g_Qhi);
    cudaGetSymbolAddress((void**)&ql, g_Qlo);
    cudaGetSymbolAddress((void**)&kh, g_Khi);
    cudaGetSymbolAddress((void**)&kl, g_Klo);

    // Q = concat(ar, own) @ Wq + bq   (split-3 bf16 tensor cores)
    {
        dim3 grid(AA / BN, MTOT / BM);
        proj_split3<<<grid, 256>>>(ar, AE, AE, own, UE, AE + UE, Wq, bq, qh, ql);
    }
    // K = enemy @ Wk + bk
    {
        dim3 grid(AA / BN, MTOT / BM);
        proj_split3<<<grid, 256>>>(enemy, UE, UE, enemy, UE, UE, Wk, bk, kh, kl);
    }
    // scores + mask
    {
        dim3 grid(UU / BN, UU / BM, BB);
        attn_split3<<<grid, 256>>>(nro, nre, nrf, out);
    }
    // softmax rows
    softmax_kernel<<<MTOT, 128>>>(out);
}